// round 11
// baseline (speedup 1.0000x reference)
#include <cuda_runtime.h>
#include <cuda_bf16.h>
#include <cuda_fp16.h>
#include <cstdint>

// Problem constants
#define BB    2
#define HW    4096
#define NTGT  4096
#define CC    512
#define HH    8
#define KNN   32
#define DH    64
#define MROWS (BB * HW)      // 8192
#define SCALE 0.125f

// ---------------- scratch (device globals: allocation-free) ----------------
__device__ float  g_q[(size_t)MROWS * CC];
__device__ __half g_kh[(size_t)MROWS * CC];
__device__ __half g_vh[(size_t)MROWS * CC];
__device__ __half g_Shi[(size_t)MROWS * CC];
__device__ __half g_Slo[(size_t)MROWS * CC];
__device__ __half g_Thi[(size_t)MROWS * CC];
__device__ __half g_Tlo[(size_t)MROWS * CC];
__device__ __half g_Ohi[(size_t)MROWS * CC];
__device__ __half g_Olo[(size_t)MROWS * CC];
__device__ __half g_Wt[4][CC * CC];            // [N][K] fp16

// ---------------- helpers ----------------------------------------------------
__device__ __forceinline__ uint32_t smem_to_u32(const void* p) {
    uint32_t a;
    asm("{ .reg .u64 t; cvta.to.shared.u64 t, %1; cvt.u32.u64 %0, t; }"
        : "=r"(a) : "l"(p));
    return a;
}
__device__ __forceinline__ void cp16(uint32_t dst, const void* src) {
    asm volatile("cp.async.cg.shared.global [%0], [%1], 16;" :: "r"(dst), "l"(src));
}
#define CP_COMMIT() asm volatile("cp.async.commit_group;" ::: "memory")
#define CP_WAIT(n)  asm volatile("cp.async.wait_group %0;" :: "n"(n) : "memory")

__device__ __forceinline__ uint32_t pack2h(__half a, __half b) {
    __half2 t = __halves2half2(a, b);
    return *reinterpret_cast<uint32_t*>(&t);
}

#define MMA_F16(d, a0, a1, a2, a3, b0, b1) \
    asm volatile( \
        "mma.sync.aligned.m16n8k16.row.col.f32.f16.f16.f32 " \
        "{%0,%1,%2,%3}, {%4,%5,%6,%7}, {%8,%9}, {%0,%1,%2,%3};" \
        : "+f"((d)[0]), "+f"((d)[1]), "+f"((d)[2]), "+f"((d)[3]) \
        : "r"(a0), "r"(a1), "r"(a2), "r"(a3), "r"(b0), "r"(b1))

// ---------------- fused weight transpose -> fp16 [N][K] ---------------------
__global__ void transpose_half_all(const float* __restrict__ W0,
                                   const float* __restrict__ W1,
                                   const float* __restrict__ W2,
                                   const float* __restrict__ W3,
                                   __half* __restrict__ out)
{
    __shared__ float t[32][33];
    const int w  = blockIdx.z;
    const float* W = (w == 0) ? W0 : (w == 1) ? W1 : (w == 2) ? W2 : W3;
    const size_t wo = (size_t)w * CC * CC;
    const int kt = blockIdx.x * 32;
    const int nt = blockIdx.y * 32;
    const int tx = threadIdx.x, ty = threadIdx.y;
    #pragma unroll
    for (int i = 0; i < 4; ++i)
        t[ty + i * 8][tx] = W[(size_t)(kt + ty + i * 8) * CC + nt + tx];
    __syncthreads();
    #pragma unroll
    for (int i = 0; i < 4; ++i) {
        float x = t[tx][ty + i * 8];
        out[wo + (size_t)(nt + ty + i * 8) * CC + kt + tx] = __float2half_rn(x);
    }
}

// ---------------- fused activation split: src + tgt -> fp16 hi/lo ----------
__global__ void __launch_bounds__(256) split2_kernel(
    const float* __restrict__ S, const float* __restrict__ T,
    __half* __restrict__ shi, __half* __restrict__ slo,
    __half* __restrict__ thi, __half* __restrict__ tlo)
{
    const int half = gridDim.x >> 1;
    const bool is_t = blockIdx.x >= half;
    const float* X = is_t ? T : S;
    __half* hi = is_t ? thi : shi;
    __half* lo = is_t ? tlo : slo;
    const int i = (is_t ? blockIdx.x - half : blockIdx.x) * 256 + threadIdx.x;
    const float4 x = reinterpret_cast<const float4*>(X)[i];
    __half h0 = __float2half_rn(x.x);
    __half h1 = __float2half_rn(x.y);
    __half h2 = __float2half_rn(x.z);
    __half h3 = __float2half_rn(x.w);
    __half l0 = __float2half_rn(x.x - __half2float(h0));
    __half l1 = __float2half_rn(x.y - __half2float(h1));
    __half l2 = __float2half_rn(x.z - __half2float(h2));
    __half l3 = __float2half_rn(x.w - __half2float(h3));
    reinterpret_cast<uint2*>(hi)[i] = make_uint2(pack2h(h0, h1), pack2h(h2, h3));
    reinterpret_cast<uint2*>(lo)[i] = make_uint2(pack2h(l0, l1), pack2h(l2, l3));
}

// ---------------- fp16 2-term mma GEMM: 128x128 tile, 2 CTAs/SM -------------
#define ROWB 144                        // 128B data + 16B pad
#define REG_SZ (128 * ROWB)             // 18432 per region (128 rows)
#define STG_SZ (3 * REG_SZ)             // 55296: [AHI | ALO | B]
#define OFF_ALO REG_SZ
#define OFF_B   (2 * REG_SZ)
#define SM_TOT  (2 * STG_SZ)            // 110592

template <typename OutT>
__device__ __forceinline__ void store2(OutT* p, float a, float b);
template <> __device__ __forceinline__ void store2<float>(float* p, float a, float b) {
    *reinterpret_cast<float2*>(p) = make_float2(a, b);
}
template <> __device__ __forceinline__ void store2<__half>(__half* p, float a, float b) {
    *reinterpret_cast<__half2*>(p) = __floats2half2_rn(a, b);
}

template <typename OutT>
__global__ void __launch_bounds__(256, 2) mma_gemm_bias(
    const __half* __restrict__ Ahi, const __half* __restrict__ Alo,
    const __half* __restrict__ Wt,
    const float* __restrict__ bias, OutT* __restrict__ C)
{
    extern __shared__ char sm[];
    const uint32_t sb = smem_to_u32(sm);
    const int tid  = threadIdx.x;
    const int wid  = tid >> 5;
    const int lane = tid & 31;
    const int bm   = blockIdx.y * 128;
    const int bn   = blockIdx.x * 128;
    const int wm   = wid & 1;           // 0..1  (m 64-half)
    const int wn   = wid >> 1;          // 0..3  (n 32-slice)

    const int lr = tid >> 3;            // 0..31
    const int lq = tid & 7;             // 16B chunk 0..7

    float acc[4][4][4];
    #pragma unroll
    for (int a = 0; a < 4; ++a)
        #pragma unroll
        for (int b = 0; b < 4; ++b)
            #pragma unroll
            for (int c = 0; c < 4; ++c) acc[a][b][c] = 0.f;

    auto load_stage = [&](int s, int kt) {
        const int kb = kt * 64;
        const uint32_t base = (uint32_t)(s * STG_SZ);
        #pragma unroll
        for (int i = 0; i < 4; ++i) {
            const int row = i * 32 + lr;
            const uint32_t so = base + (uint32_t)(row * ROWB + lq * 16);
            const size_t  ga = (size_t)(bm + row) * CC + kb + lq * 8;
            const size_t  gb = (size_t)(bn + row) * CC + kb + lq * 8;
            cp16(sb + so, Ahi + ga);
            cp16(sb + OFF_ALO + so, Alo + ga);
            cp16(sb + OFF_B + so, Wt + gb);
        }
    };

    load_stage(0, 0);
    CP_COMMIT();

    const int sub16 = lane & 15;
    const int ahalf = lane >> 4;
    const int bn8   = lane & 7;
    const int bk16  = (lane >> 3) & 1;

    #pragma unroll 1
    for (int kt = 0; kt < 8; ++kt) {
        const int s = kt & 1;
        CP_WAIT(0);
        __syncthreads();
        if (kt + 1 < 8) {
            load_stage(s ^ 1, kt + 1);
            CP_COMMIT();
        }

        const uint32_t aBase = sb + (uint32_t)(s * STG_SZ);
        const uint32_t bBase = aBase + OFF_B;

        #pragma unroll
        for (int s2 = 0; s2 < 4; ++s2) {
            const int kbyte = s2 * 32;

            uint32_t bh[4][2];
            #pragma unroll
            for (int nf = 0; nf < 4; ++nf) {
                const uint32_t brow = (uint32_t)(wn * 32 + nf * 8 + bn8);
                const uint32_t ba = bBase + brow * ROWB + kbyte + bk16 * 16;
                asm volatile(
                    "ldmatrix.sync.aligned.m8n8.x2.shared.b16 {%0,%1}, [%2];"
                    : "=r"(bh[nf][0]), "=r"(bh[nf][1]) : "r"(ba));
            }
            uint32_t ah[4][4], al[4][4];
            #pragma unroll
            for (int mf = 0; mf < 4; ++mf) {
                const uint32_t arow = (uint32_t)(wm * 64 + mf * 16 + sub16);
                const uint32_t aa = aBase + arow * ROWB + kbyte + ahalf * 16;
                asm volatile(
                    "ldmatrix.sync.aligned.m8n8.x4.shared.b16 {%0,%1,%2,%3}, [%4];"
                    : "=r"(ah[mf][0]), "=r"(ah[mf][1]), "=r"(ah[mf][2]), "=r"(ah[mf][3])
                    : "r"(aa));
                asm volatile(
                    "ldmatrix.sync.aligned.m8n8.x4.shared.b16 {%0,%1,%2,%3}, [%4];"
                    : "=r"(al[mf][0]), "=r"(al[mf][1]), "=r"(al[mf][2]), "=r"(al[mf][3])
                    : "r"(aa + OFF_ALO));
            }

            #pragma unroll
            for (int mf = 0; mf < 4; ++mf)
                #pragma unroll
                for (int nf = 0; nf < 4; ++nf)
                    MMA_F16(acc[mf][nf], ah[mf][0], ah[mf][1], ah[mf][2], ah[mf][3],
                            bh[nf][0], bh[nf][1]);
            #pragma unroll
            for (int mf = 0; mf < 4; ++mf)
                #pragma unroll
                for (int nf = 0; nf < 4; ++nf)
                    MMA_F16(acc[mf][nf], al[mf][0], al[mf][1], al[mf][2], al[mf][3],
                            bh[nf][0], bh[nf][1]);
        }
    }

    const int g = lane >> 2;
    const int t = lane & 3;
    #pragma unroll
    for (int mf = 0; mf < 4; ++mf) {
        const int row = bm + wm * 64 + mf * 16 + g;
        #pragma unroll
        for (int nf = 0; nf < 4; ++nf) {
            const int col = bn + wn * 32 + nf * 8 + 2 * t;
            const float b0 = __ldg(bias + col);
            const float b1 = __ldg(bias + col + 1);
            float* d = acc[mf][nf];
            store2<OutT>(C + (size_t)row * CC + col, d[0] + b0, d[1] + b1);
            store2<OutT>(C + (size_t)(row + 8) * CC + col, d[2] + b0, d[3] + b1);
        }
    }
}

// ---------------- gather attention: fp16 K/V, one warp per (b,q) ------------
__global__ void __launch_bounds__(256) attn_kernel(
    const float* __restrict__ q, const __half* __restrict__ k,
    const __half* __restrict__ v, const int* __restrict__ indices,
    const float* __restrict__ weights,
    __half* __restrict__ ohi, __half* __restrict__ olo)
{
    __shared__ float slog[8 * 8 * 33];
    const int wid  = threadIdx.x >> 5;
    const int lane = threadIdx.x & 31;
    const int bq   = blockIdx.x * 8 + wid;
    const int b    = bq >> 12;
    float* sl = slog + wid * (8 * 33);

    const __half* kb = k + (size_t)b * NTGT * CC;
    const __half* vb = v + (size_t)b * NTGT * CC;

    const int idxl = indices[(size_t)bq * KNN + lane];

    float qf[2][8];
    {
        const float4* qrow = reinterpret_cast<const float4*>(q + (size_t)bq * CC);
        #pragma unroll
        for (int i = 0; i < 2; ++i) {
            float4 a = qrow[i * 64 + lane * 2];
            float4 c = qrow[i * 64 + lane * 2 + 1];
            qf[i][0] = a.x; qf[i][1] = a.y; qf[i][2] = a.z; qf[i][3] = a.w;
            qf[i][4] = c.x; qf[i][5] = c.y; qf[i][6] = c.z; qf[i][7] = c.w;
        }
    }

    #pragma unroll 4
    for (int j = 0; j < KNN; ++j) {
        const int ij = __shfl_sync(0xffffffffu, idxl, j);
        const uint4* krow = reinterpret_cast<const uint4*>(kb + (size_t)ij * CC);
        float part[2];
        #pragma unroll
        for (int i = 0; i < 2; ++i) {
            const uint4 kk = krow[i * 32 + lane];
            const __half2* kh = reinterpret_cast<const __half2*>(&kk);
            float p = 0.f;
            #pragma unroll
            for (int h2 = 0; h2 < 4; ++h2) {
                const float2 kf = __half22float2(kh[h2]);
                p = fmaf(qf[i][2 * h2], kf.x, p);
                p = fmaf(qf[i][2 * h2 + 1], kf.y, p);
            }
            part[i] = p;
        }
        #pragma unroll
        for (int off = 4; off >= 1; off >>= 1) {
            part[0] += __shfl_xor_sync(0xffffffffu, part[0], off);
            part[1] += __shfl_xor_sync(0xffffffffu, part[1], off);
        }
        if ((lane & 7) == 0) {
            sl[(0 * 4 + (lane >> 3)) * 33 + j] = part[0];
            sl[(1 * 4 + (lane >> 3)) * 33 + j] = part[1];
        }
    }
    __syncwarp();

    {
        const int h  = lane >> 2;
        const int j0 = lane & 3;
        float vals[8];
        #pragma unroll
        for (int t = 0; t < 8; ++t) {
            const int j = j0 + 4 * t;
            vals[t] = sl[h * 33 + j] * SCALE + weights[(size_t)bq * KNN + j];
        }
        float m = vals[0];
        #pragma unroll
        for (int t = 1; t < 8; ++t) m = fmaxf(m, vals[t]);
        m = fmaxf(m, __shfl_xor_sync(0xffffffffu, m, 1));
        m = fmaxf(m, __shfl_xor_sync(0xffffffffu, m, 2));
        float s = 0.f;
        #pragma unroll
        for (int t = 0; t < 8; ++t) { vals[t] = __expf(vals[t] - m); s += vals[t]; }
        s += __shfl_xor_sync(0xffffffffu, s, 1);
        s += __shfl_xor_sync(0xffffffffu, s, 2);
        const float inv = 1.f / s;
        #pragma unroll
        for (int t = 0; t < 8; ++t) sl[h * 33 + j0 + 4 * t] = vals[t] * inv;
    }
    __syncwarp();

    float acc[2][8];
    #pragma unroll
    for (int i = 0; i < 2; ++i)
        #pragma unroll
        for (int d = 0; d < 8; ++d) acc[i][d] = 0.f;

    const int hsub = lane >> 3;
    #pragma unroll 4
    for (int j = 0; j < KNN; ++j) {
        const int ij = __shfl_sync(0xffffffffu, idxl, j);
        const uint4* vrow = reinterpret_cast<const uint4*>(vb + (size_t)ij * CC);
        #pragma unroll
        for (int i = 0; i < 2; ++i) {
            const float pj = sl[(i * 4 + hsub) * 33 + j];
            const uint4 vv = vrow[i * 32 + lane];
            const __half2* vh = reinterpret_cast<const __half2*>(&vv);
            #pragma unroll
            for (int h2 = 0; h2 < 4; ++h2) {
                const float2 vf = __half22float2(vh[h2]);
                acc[i][2 * h2]     = fmaf(pj, vf.x, acc[i][2 * h2]);
                acc[i][2 * h2 + 1] = fmaf(pj, vf.y, acc[i][2 * h2 + 1]);
            }
        }
    }

    #pragma unroll
    for (int i = 0; i < 2; ++i) {
        const size_t d = (size_t)bq * CC + i * 256 + lane * 8;
        uint32_t hw[4], lw[4];
        #pragma unroll
        for (int p = 0; p < 4; ++p) {
            float x0 = acc[i][2 * p], x1 = acc[i][2 * p + 1];
            __half h0 = __float2half_rn(x0);
            __half h1 = __float2half_rn(x1);
            __half l0 = __float2half_rn(x0 - __half2float(h0));
            __half l1 = __float2half_rn(x1 - __half2float(h1));
            hw[p] = pack2h(h0, h1);
            lw[p] = pack2h(l0, l1);
        }
        *reinterpret_cast<uint4*>(ohi + d) = make_uint4(hw[0], hw[1], hw[2], hw[3]);
        *reinterpret_cast<uint4*>(olo + d) = make_uint4(lw[0], lw[1], lw[2], lw[3]);
    }
}

// ---------------- launch ----------------------------------------------------
extern "C" void kernel_launch(void* const* d_in, const int* in_sizes, int n_in,
                              void* d_out, int out_size)
{
    const float* src = (const float*)d_in[0];
    const float* tgt = (const float*)d_in[1];
    const int*   idx = (const int*)d_in[2];
    const float* wts = (const float*)d_in[3];
    const float* Wq  = (const float*)d_in[4];
    const float* bq  = (const float*)d_in[5];
    const float* Wk  = (const float*)d_in[6];
    const float* bk  = (const float*)d_in[7];
    const float* Wv  = (const float*)d_in[8];
    const float* bv  = (const float*)d_in[9];
    const float* Wo  = (const float*)d_in[10];
    const float* bo  = (const float*)d_in[11];
    float*       out = (float*)d_out;

    void *pq, *pkh, *pvh, *pshi, *pslo, *pthi, *ptlo, *pohi, *polo, *pwt;
    cudaGetSymbolAddress(&pq, g_q);
    cudaGetSymbolAddress(&pkh, g_kh);
    cudaGetSymbolAddress(&pvh, g_vh);
    cudaGetSymbolAddress(&pshi, g_Shi);
    cudaGetSymbolAddress(&pslo, g_Slo);
    cudaGetSymbolAddress(&pthi, g_Thi);
    cudaGetSymbolAddress(&ptlo, g_Tlo);
    cudaGetSymbolAddress(&pohi, g_Ohi);
    cudaGetSymbolAddress(&polo, g_Olo);
    cudaGetSymbolAddress(&pwt, g_Wt);
    float*  gq  = (float*)pq;
    __half* gkh = (__half*)pkh;
    __half* gvh = (__half*)pvh;
    __half* shi = (__half*)pshi;
    __half* slo = (__half*)pslo;
    __half* thi = (__half*)pthi;
    __half* tlo = (__half*)ptlo;
    __half* ohi = (__half*)pohi;
    __half* olo = (__half*)polo;
    __half* wt  = (__half*)pwt;

    static bool attr_set = false;
    if (!attr_set) {
        cudaFuncSetAttribute(mma_gemm_bias<float>,
                             cudaFuncAttributeMaxDynamicSharedMemorySize, SM_TOT);
        cudaFuncSetAttribute(mma_gemm_bias<__half>,
                             cudaFuncAttributeMaxDynamicSharedMemorySize, SM_TOT);
        attr_set = true;
    }

    const size_t WS = (size_t)CC * CC;

    dim3 tgrid(CC / 32, CC / 32, 4), tblk(32, 8);
    transpose_half_all<<<tgrid, tblk>>>(Wq, Wk, Wv, Wo, wt);

    const int nsplit = MROWS * CC / 4 / 256;
    split2_kernel<<<2 * nsplit, 256>>>(src, tgt, shi, slo, thi, tlo);

    dim3 ggrid(CC / 128, MROWS / 128);   // (4, 64) = 256 CTAs, 2/SM
    mma_gemm_bias<float><<<ggrid, 256, SM_TOT>>>(shi, slo, wt + 0 * WS, bq, gq);
    mma_gemm_bias<__half><<<ggrid, 256, SM_TOT>>>(thi, tlo, wt + 1 * WS, bk, gkh);
    mma_gemm_bias<__half><<<ggrid, 256, SM_TOT>>>(thi, tlo, wt + 2 * WS, bv, gvh);

    attn_kernel<<<BB * HW / 8, 256>>>(gq, gkh, gvh, idx, wts, ohi, olo);

    mma_gemm_bias<float><<<ggrid, 256, SM_TOT>>>(ohi, olo, wt + 3 * WS, bo, out);
}

// round 12
// speedup vs baseline: 1.2212x; 1.2212x over previous
#include <cuda_runtime.h>
#include <cuda_bf16.h>
#include <cuda_fp16.h>
#include <cstdint>

// Problem constants
#define BB    2
#define HW    4096
#define NTGT  4096
#define CC    512
#define HH    8
#define KNN   32
#define DH    64
#define MROWS (BB * HW)      // 8192
#define SCALE 0.125f

// ---------------- scratch (device globals: allocation-free) ----------------
__device__ float  g_q[(size_t)MROWS * CC];
__device__ __half g_kh[(size_t)MROWS * CC];
__device__ __half g_vh[(size_t)MROWS * CC];
__device__ __half g_Sh[(size_t)MROWS * CC];    // src fp16
__device__ __half g_Th[(size_t)MROWS * CC];    // tgt fp16
__device__ __half g_Ohi[(size_t)MROWS * CC];   // attn-out fp16 hi/lo
__device__ __half g_Olo[(size_t)MROWS * CC];
__device__ __half g_Wt[4][CC * CC];            // [N][K] fp16

// ---------------- helpers ----------------------------------------------------
__device__ __forceinline__ uint32_t smem_to_u32(const void* p) {
    uint32_t a;
    asm("{ .reg .u64 t; cvta.to.shared.u64 t, %1; cvt.u32.u64 %0, t; }"
        : "=r"(a) : "l"(p));
    return a;
}
__device__ __forceinline__ void cp16(uint32_t dst, const void* src) {
    asm volatile("cp.async.cg.shared.global [%0], [%1], 16;" :: "r"(dst), "l"(src));
}
#define CP_COMMIT() asm volatile("cp.async.commit_group;" ::: "memory")
#define CP_WAIT(n)  asm volatile("cp.async.wait_group %0;" :: "n"(n) : "memory")

__device__ __forceinline__ uint32_t pack2h(__half a, __half b) {
    __half2 t = __halves2half2(a, b);
    return *reinterpret_cast<uint32_t*>(&t);
}

#define MMA_F16(d, a0, a1, a2, a3, b0, b1) \
    asm volatile( \
        "mma.sync.aligned.m16n8k16.row.col.f32.f16.f16.f32 " \
        "{%0,%1,%2,%3}, {%4,%5,%6,%7}, {%8,%9}, {%0,%1,%2,%3};" \
        : "+f"((d)[0]), "+f"((d)[1]), "+f"((d)[2]), "+f"((d)[3]) \
        : "r"(a0), "r"(a1), "r"(a2), "r"(a3), "r"(b0), "r"(b1))

// ---------------- fused weight transpose -> fp16 [N][K] ---------------------
__global__ void transpose_half_all(const float* __restrict__ W0,
                                   const float* __restrict__ W1,
                                   const float* __restrict__ W2,
                                   const float* __restrict__ W3,
                                   __half* __restrict__ out)
{
    __shared__ float t[32][33];
    const int w  = blockIdx.z;
    const float* W = (w == 0) ? W0 : (w == 1) ? W1 : (w == 2) ? W2 : W3;
    const size_t wo = (size_t)w * CC * CC;
    const int kt = blockIdx.x * 32;
    const int nt = blockIdx.y * 32;
    const int tx = threadIdx.x, ty = threadIdx.y;
    #pragma unroll
    for (int i = 0; i < 4; ++i)
        t[ty + i * 8][tx] = W[(size_t)(kt + ty + i * 8) * CC + nt + tx];
    __syncthreads();
    #pragma unroll
    for (int i = 0; i < 4; ++i) {
        float x = t[tx][ty + i * 8];
        out[wo + (size_t)(nt + ty + i * 8) * CC + kt + tx] = __float2half_rn(x);
    }
}

// ---------------- fused activation convert: src + tgt -> fp16 --------------
__global__ void __launch_bounds__(256) conv2_kernel(
    const float* __restrict__ S, const float* __restrict__ T,
    __half* __restrict__ sh, __half* __restrict__ th)
{
    const int half = gridDim.x >> 1;
    const bool is_t = blockIdx.x >= half;
    const float* X = is_t ? T : S;
    __half* o = is_t ? th : sh;
    const int i = (is_t ? blockIdx.x - half : blockIdx.x) * 256 + threadIdx.x;
    const float4 x = reinterpret_cast<const float4*>(X)[i];
    reinterpret_cast<uint2*>(o)[i] =
        make_uint2(pack2h(__float2half_rn(x.x), __float2half_rn(x.y)),
                   pack2h(__float2half_rn(x.z), __float2half_rn(x.w)));
}

// ---------------- fp16 mma GEMM: 128x128 tile, TERMS = 1 or 2 ---------------
#define ROWB 144                        // 128B data + 16B pad
#define REG_SZ (128 * ROWB)             // 18432 per region (128 rows)

template <typename OutT>
__device__ __forceinline__ void store2(OutT* p, float a, float b);
template <> __device__ __forceinline__ void store2<float>(float* p, float a, float b) {
    *reinterpret_cast<float2*>(p) = make_float2(a, b);
}
template <> __device__ __forceinline__ void store2<__half>(__half* p, float a, float b) {
    *reinterpret_cast<__half2*>(p) = __floats2half2_rn(a, b);
}

template <typename OutT, int TERMS>
__global__ void __launch_bounds__(256, 2) mma_gemm_bias(
    const __half* __restrict__ Ahi, const __half* __restrict__ Alo,
    const __half* __restrict__ Wt,
    const float* __restrict__ bias, OutT* __restrict__ C)
{
    constexpr uint32_t OFF_ALO = REG_SZ;                  // valid when TERMS==2
    constexpr uint32_t OFF_B   = TERMS * REG_SZ;
    constexpr uint32_t STG_SZ  = (TERMS + 1) * REG_SZ;

    extern __shared__ char sm[];
    const uint32_t sb = smem_to_u32(sm);
    const int tid  = threadIdx.x;
    const int wid  = tid >> 5;
    const int lane = tid & 31;
    const int bm   = blockIdx.y * 128;
    const int bn   = blockIdx.x * 128;
    const int wm   = wid & 1;
    const int wn   = wid >> 1;

    const int lr = tid >> 3;            // 0..31
    const int lq = tid & 7;             // 16B chunk

    float acc[4][4][4];
    #pragma unroll
    for (int a = 0; a < 4; ++a)
        #pragma unroll
        for (int b = 0; b < 4; ++b)
            #pragma unroll
            for (int c = 0; c < 4; ++c) acc[a][b][c] = 0.f;

    auto load_stage = [&](int s, int kt) {
        const int kb = kt * 64;
        const uint32_t base = (uint32_t)(s * STG_SZ);
        #pragma unroll
        for (int i = 0; i < 4; ++i) {
            const int row = i * 32 + lr;
            const uint32_t so = base + (uint32_t)(row * ROWB + lq * 16);
            const size_t  ga = (size_t)(bm + row) * CC + kb + lq * 8;
            const size_t  gb = (size_t)(bn + row) * CC + kb + lq * 8;
            cp16(sb + so, Ahi + ga);
            if (TERMS == 2) cp16(sb + OFF_ALO + so, Alo + ga);
            cp16(sb + OFF_B + so, Wt + gb);
        }
    };

    load_stage(0, 0);
    CP_COMMIT();

    const int sub16 = lane & 15;
    const int ahalf = lane >> 4;
    const int bn8   = lane & 7;
    const int bk16  = (lane >> 3) & 1;

    #pragma unroll 1
    for (int kt = 0; kt < 8; ++kt) {
        const int s = kt & 1;
        CP_WAIT(0);
        __syncthreads();
        if (kt + 1 < 8) {
            load_stage(s ^ 1, kt + 1);
            CP_COMMIT();
        }

        const uint32_t aBase = sb + (uint32_t)(s * STG_SZ);
        const uint32_t bBase = aBase + OFF_B;

        #pragma unroll
        for (int s2 = 0; s2 < 4; ++s2) {
            const int kbyte = s2 * 32;

            uint32_t bh[4][2];
            #pragma unroll
            for (int nf = 0; nf < 4; ++nf) {
                const uint32_t brow = (uint32_t)(wn * 32 + nf * 8 + bn8);
                const uint32_t ba = bBase + brow * ROWB + kbyte + bk16 * 16;
                asm volatile(
                    "ldmatrix.sync.aligned.m8n8.x2.shared.b16 {%0,%1}, [%2];"
                    : "=r"(bh[nf][0]), "=r"(bh[nf][1]) : "r"(ba));
            }
            uint32_t ah[4][4], al[4][4];
            #pragma unroll
            for (int mf = 0; mf < 4; ++mf) {
                const uint32_t arow = (uint32_t)(wm * 64 + mf * 16 + sub16);
                const uint32_t aa = aBase + arow * ROWB + kbyte + ahalf * 16;
                asm volatile(
                    "ldmatrix.sync.aligned.m8n8.x4.shared.b16 {%0,%1,%2,%3}, [%4];"
                    : "=r"(ah[mf][0]), "=r"(ah[mf][1]), "=r"(ah[mf][2]), "=r"(ah[mf][3])
                    : "r"(aa));
                if (TERMS == 2) {
                    asm volatile(
                        "ldmatrix.sync.aligned.m8n8.x4.shared.b16 {%0,%1,%2,%3}, [%4];"
                        : "=r"(al[mf][0]), "=r"(al[mf][1]), "=r"(al[mf][2]), "=r"(al[mf][3])
                        : "r"(aa + OFF_ALO));
                }
            }

            #pragma unroll
            for (int mf = 0; mf < 4; ++mf)
                #pragma unroll
                for (int nf = 0; nf < 4; ++nf)
                    MMA_F16(acc[mf][nf], ah[mf][0], ah[mf][1], ah[mf][2], ah[mf][3],
                            bh[nf][0], bh[nf][1]);
            if (TERMS == 2) {
                #pragma unroll
                for (int mf = 0; mf < 4; ++mf)
                    #pragma unroll
                    for (int nf = 0; nf < 4; ++nf)
                        MMA_F16(acc[mf][nf], al[mf][0], al[mf][1], al[mf][2], al[mf][3],
                                bh[nf][0], bh[nf][1]);
            }
        }
    }

    const int g = lane >> 2;
    const int t = lane & 3;
    #pragma unroll
    for (int mf = 0; mf < 4; ++mf) {
        const int row = bm + wm * 64 + mf * 16 + g;
        #pragma unroll
        for (int nf = 0; nf < 4; ++nf) {
            const int col = bn + wn * 32 + nf * 8 + 2 * t;
            const float b0 = __ldg(bias + col);
            const float b1 = __ldg(bias + col + 1);
            float* d = acc[mf][nf];
            store2<OutT>(C + (size_t)row * CC + col, d[0] + b0, d[1] + b1);
            store2<OutT>(C + (size_t)(row + 8) * CC + col, d[2] + b0, d[3] + b1);
        }
    }
}

// ---------------- gather attention: fp16 K/V, one warp per (b,q) ------------
__global__ void __launch_bounds__(256) attn_kernel(
    const float* __restrict__ q, const __half* __restrict__ k,
    const __half* __restrict__ v, const int* __restrict__ indices,
    const float* __restrict__ weights,
    __half* __restrict__ ohi, __half* __restrict__ olo)
{
    __shared__ float slog[8 * 8 * 33];
    const int wid  = threadIdx.x >> 5;
    const int lane = threadIdx.x & 31;
    const int bq   = blockIdx.x * 8 + wid;
    const int b    = bq >> 12;
    float* sl = slog + wid * (8 * 33);

    const __half* kb = k + (size_t)b * NTGT * CC;
    const __half* vb = v + (size_t)b * NTGT * CC;

    const int idxl = indices[(size_t)bq * KNN + lane];

    float qf[2][8];
    {
        const float4* qrow = reinterpret_cast<const float4*>(q + (size_t)bq * CC);
        #pragma unroll
        for (int i = 0; i < 2; ++i) {
            float4 a = qrow[i * 64 + lane * 2];
            float4 c = qrow[i * 64 + lane * 2 + 1];
            qf[i][0] = a.x; qf[i][1] = a.y; qf[i][2] = a.z; qf[i][3] = a.w;
            qf[i][4] = c.x; qf[i][5] = c.y; qf[i][6] = c.z; qf[i][7] = c.w;
        }
    }

    #pragma unroll 4
    for (int j = 0; j < KNN; ++j) {
        const int ij = __shfl_sync(0xffffffffu, idxl, j);
        const uint4* krow = reinterpret_cast<const uint4*>(kb + (size_t)ij * CC);
        float part[2];
        #pragma unroll
        for (int i = 0; i < 2; ++i) {
            const uint4 kk = krow[i * 32 + lane];
            const __half2* kh = reinterpret_cast<const __half2*>(&kk);
            float p = 0.f;
            #pragma unroll
            for (int h2 = 0; h2 < 4; ++h2) {
                const float2 kf = __half22float2(kh[h2]);
                p = fmaf(qf[i][2 * h2], kf.x, p);
                p = fmaf(qf[i][2 * h2 + 1], kf.y, p);
            }
            part[i] = p;
        }
        #pragma unroll
        for (int off = 4; off >= 1; off >>= 1) {
            part[0] += __shfl_xor_sync(0xffffffffu, part[0], off);
            part[1] += __shfl_xor_sync(0xffffffffu, part[1], off);
        }
        if ((lane & 7) == 0) {
            sl[(0 * 4 + (lane >> 3)) * 33 + j] = part[0];
            sl[(1 * 4 + (lane >> 3)) * 33 + j] = part[1];
        }
    }
    __syncwarp();

    {
        const int h  = lane >> 2;
        const int j0 = lane & 3;
        float vals[8];
        #pragma unroll
        for (int t = 0; t < 8; ++t) {
            const int j = j0 + 4 * t;
            vals[t] = sl[h * 33 + j] * SCALE + weights[(size_t)bq * KNN + j];
        }
        float m = vals[0];
        #pragma unroll
        for (int t = 1; t < 8; ++t) m = fmaxf(m, vals[t]);
        m = fmaxf(m, __shfl_xor_sync(0xffffffffu, m, 1));
        m = fmaxf(m, __shfl_xor_sync(0xffffffffu, m, 2));
        float s = 0.f;
        #pragma unroll
        for (int t = 0; t < 8; ++t) { vals[t] = __expf(vals[t] - m); s += vals[t]; }
        s += __shfl_xor_sync(0xffffffffu, s, 1);
        s += __shfl_xor_sync(0xffffffffu, s, 2);
        const float inv = 1.f / s;
        #pragma unroll
        for (int t = 0; t < 8; ++t) sl[h * 33 + j0 + 4 * t] = vals[t] * inv;
    }
    __syncwarp();

    float acc[2][8];
    #pragma unroll
    for (int i = 0; i < 2; ++i)
        #pragma unroll
        for (int d = 0; d < 8; ++d) acc[i][d] = 0.f;

    const int hsub = lane >> 3;
    #pragma unroll 4
    for (int j = 0; j < KNN; ++j) {
        const int ij = __shfl_sync(0xffffffffu, idxl, j);
        const uint4* vrow = reinterpret_cast<const uint4*>(vb + (size_t)ij * CC);
        #pragma unroll
        for (int i = 0; i < 2; ++i) {
            const float pj = sl[(i * 4 + hsub) * 33 + j];
            const uint4 vv = vrow[i * 32 + lane];
            const __half2* vh = reinterpret_cast<const __half2*>(&vv);
            #pragma unroll
            for (int h2 = 0; h2 < 4; ++h2) {
                const float2 vf = __half22float2(vh[h2]);
                acc[i][2 * h2]     = fmaf(pj, vf.x, acc[i][2 * h2]);
                acc[i][2 * h2 + 1] = fmaf(pj, vf.y, acc[i][2 * h2 + 1]);
            }
        }
    }

    #pragma unroll
    for (int i = 0; i < 2; ++i) {
        const size_t d = (size_t)bq * CC + i * 256 + lane * 8;
        uint32_t hw[4], lw[4];
        #pragma unroll
        for (int p = 0; p < 4; ++p) {
            float x0 = acc[i][2 * p], x1 = acc[i][2 * p + 1];
            __half h0 = __float2half_rn(x0);
            __half h1 = __float2half_rn(x1);
            __half l0 = __float2half_rn(x0 - __half2float(h0));
            __half l1 = __float2half_rn(x1 - __half2float(h1));
            hw[p] = pack2h(h0, h1);
            lw[p] = pack2h(l0, l1);
        }
        *reinterpret_cast<uint4*>(ohi + d) = make_uint4(hw[0], hw[1], hw[2], hw[3]);
        *reinterpret_cast<uint4*>(olo + d) = make_uint4(lw[0], lw[1], lw[2], lw[3]);
    }
}

// ---------------- launch ----------------------------------------------------
extern "C" void kernel_launch(void* const* d_in, const int* in_sizes, int n_in,
                              void* d_out, int out_size)
{
    const float* src = (const float*)d_in[0];
    const float* tgt = (const float*)d_in[1];
    const int*   idx = (const int*)d_in[2];
    const float* wts = (const float*)d_in[3];
    const float* Wq  = (const float*)d_in[4];
    const float* bq  = (const float*)d_in[5];
    const float* Wk  = (const float*)d_in[6];
    const float* bk  = (const float*)d_in[7];
    const float* Wv  = (const float*)d_in[8];
    const float* bv  = (const float*)d_in[9];
    const float* Wo  = (const float*)d_in[10];
    const float* bo  = (const float*)d_in[11];
    float*       out = (float*)d_out;

    void *pq, *pkh, *pvh, *psh, *pth, *pohi, *polo, *pwt;
    cudaGetSymbolAddress(&pq, g_q);
    cudaGetSymbolAddress(&pkh, g_kh);
    cudaGetSymbolAddress(&pvh, g_vh);
    cudaGetSymbolAddress(&psh, g_Sh);
    cudaGetSymbolAddress(&pth, g_Th);
    cudaGetSymbolAddress(&pohi, g_Ohi);
    cudaGetSymbolAddress(&polo, g_Olo);
    cudaGetSymbolAddress(&pwt, g_Wt);
    float*  gq  = (float*)pq;
    __half* gkh = (__half*)pkh;
    __half* gvh = (__half*)pvh;
    __half* sh  = (__half*)psh;
    __half* th  = (__half*)pth;
    __half* ohi = (__half*)pohi;
    __half* olo = (__half*)polo;
    __half* wt  = (__half*)pwt;

    constexpr int SM1 = 2 * 2 * REG_SZ;   // TERMS=1: 73728
    constexpr int SM2 = 2 * 3 * REG_SZ;   // TERMS=2: 110592

    static bool attr_set = false;
    if (!attr_set) {
        cudaFuncSetAttribute(mma_gemm_bias<float, 1>,
                             cudaFuncAttributeMaxDynamicSharedMemorySize, SM1);
        cudaFuncSetAttribute(mma_gemm_bias<__half, 1>,
                             cudaFuncAttributeMaxDynamicSharedMemorySize, SM1);
        cudaFuncSetAttribute(mma_gemm_bias<float, 2>,
                             cudaFuncAttributeMaxDynamicSharedMemorySize, SM2);
        attr_set = true;
    }

    const size_t WS = (size_t)CC * CC;

    dim3 tgrid(CC / 32, CC / 32, 4), tblk(32, 8);
    transpose_half_all<<<tgrid, tblk>>>(Wq, Wk, Wv, Wo, wt);

    const int nconv = MROWS * CC / 4 / 256;
    conv2_kernel<<<2 * nconv, 256>>>(src, tgt, sh, th);

    dim3 ggrid(CC / 128, MROWS / 128);   // (4, 64) = 256 CTAs, 2/SM
    mma_gemm_bias<float, 1><<<ggrid, 256, SM1>>>(sh, nullptr, wt + 0 * WS, bq, gq);
    mma_gemm_bias<__half, 1><<<ggrid, 256, SM1>>>(th, nullptr, wt + 1 * WS, bk, gkh);
    mma_gemm_bias<__half, 1><<<ggrid, 256, SM1>>>(th, nullptr, wt + 2 * WS, bv, gvh);

    attn_kernel<<<BB * HW / 8, 256>>>(gq, gkh, gvh, idx, wts, ohi, olo);

    mma_gemm_bias<float, 2><<<ggrid, 256, SM2>>>(ohi, olo, wt + 3 * WS, bo, out);
}

// round 13
// speedup vs baseline: 1.3874x; 1.1361x over previous
#include <cuda_runtime.h>
#include <cuda_bf16.h>
#include <cuda_fp16.h>
#include <cstdint>

// Problem constants
#define BB    2
#define HW    4096
#define NTGT  4096
#define CC    512
#define HH    8
#define KNN   32
#define DH    64
#define MROWS (BB * HW)      // 8192
#define SCALE 0.125f

// ---------------- scratch (device globals: allocation-free) ----------------
__device__ float  g_q[(size_t)MROWS * CC];
__device__ __half g_kh[(size_t)MROWS * CC];
__device__ __half g_vh[(size_t)MROWS * CC];
__device__ __half g_Sh[(size_t)MROWS * CC];    // src fp16
__device__ __half g_Th[(size_t)MROWS * CC];    // tgt fp16
__device__ __half g_Oh[(size_t)MROWS * CC];    // attn-out fp16
__device__ __half g_Wt[4][CC * CC];            // [N][K] fp16

// ---------------- helpers ----------------------------------------------------
__device__ __forceinline__ uint32_t smem_to_u32(const void* p) {
    uint32_t a;
    asm("{ .reg .u64 t; cvta.to.shared.u64 t, %1; cvt.u32.u64 %0, t; }"
        : "=r"(a) : "l"(p));
    return a;
}
__device__ __forceinline__ void cp16(uint32_t dst, const void* src) {
    asm volatile("cp.async.cg.shared.global [%0], [%1], 16;" :: "r"(dst), "l"(src));
}
#define CP_COMMIT() asm volatile("cp.async.commit_group;" ::: "memory")
#define CP_WAIT(n)  asm volatile("cp.async.wait_group %0;" :: "n"(n) : "memory")

__device__ __forceinline__ uint32_t pack2h(__half a, __half b) {
    __half2 t = __halves2half2(a, b);
    return *reinterpret_cast<uint32_t*>(&t);
}

#define MMA_F16(d, a0, a1, a2, a3, b0, b1) \
    asm volatile( \
        "mma.sync.aligned.m16n8k16.row.col.f32.f16.f16.f32 " \
        "{%0,%1,%2,%3}, {%4,%5,%6,%7}, {%8,%9}, {%0,%1,%2,%3};" \
        : "+f"((d)[0]), "+f"((d)[1]), "+f"((d)[2]), "+f"((d)[3]) \
        : "r"(a0), "r"(a1), "r"(a2), "r"(a3), "r"(b0), "r"(b1))

// ---------------- fused weight transpose -> fp16 [N][K] ---------------------
__global__ void transpose_half_all(const float* __restrict__ W0,
                                   const float* __restrict__ W1,
                                   const float* __restrict__ W2,
                                   const float* __restrict__ W3,
                                   __half* __restrict__ out)
{
    __shared__ float t[32][33];
    const int w  = blockIdx.z;
    const float* W = (w == 0) ? W0 : (w == 1) ? W1 : (w == 2) ? W2 : W3;
    const size_t wo = (size_t)w * CC * CC;
    const int kt = blockIdx.x * 32;
    const int nt = blockIdx.y * 32;
    const int tx = threadIdx.x, ty = threadIdx.y;
    #pragma unroll
    for (int i = 0; i < 4; ++i)
        t[ty + i * 8][tx] = W[(size_t)(kt + ty + i * 8) * CC + nt + tx];
    __syncthreads();
    #pragma unroll
    for (int i = 0; i < 4; ++i) {
        float x = t[tx][ty + i * 8];
        out[wo + (size_t)(nt + ty + i * 8) * CC + kt + tx] = __float2half_rn(x);
    }
}

// ---------------- fused activation convert: src + tgt -> fp16 --------------
__global__ void __launch_bounds__(256) conv2_kernel(
    const float* __restrict__ S, const float* __restrict__ T,
    __half* __restrict__ sh, __half* __restrict__ th)
{
    const int half = gridDim.x >> 1;
    const bool is_t = blockIdx.x >= half;
    const float* X = is_t ? T : S;
    __half* o = is_t ? th : sh;
    const int i = (is_t ? blockIdx.x - half : blockIdx.x) * 256 + threadIdx.x;
    const float4 x = reinterpret_cast<const float4*>(X)[i];
    reinterpret_cast<uint2*>(o)[i] =
        make_uint2(pack2h(__float2half_rn(x.x), __float2half_rn(x.y)),
                   pack2h(__float2half_rn(x.z), __float2half_rn(x.w)));
}

// ---------------- fp16 single-term mma GEMM body ----------------------------
#define ROWB 144                        // 128B data + 16B pad
#define REG_SZ (128 * ROWB)             // 18432 per region (128 rows)
#define STG_SZ (2 * REG_SZ)             // [A | B]
#define OFF_B  REG_SZ
#define SM_TOT (2 * STG_SZ)             // 73728

template <typename OutT>
__device__ __forceinline__ void store2(OutT* p, float a, float b);
template <> __device__ __forceinline__ void store2<float>(float* p, float a, float b) {
    *reinterpret_cast<float2*>(p) = make_float2(a, b);
}
template <> __device__ __forceinline__ void store2<__half>(__half* p, float a, float b) {
    *reinterpret_cast<__half2*>(p) = __floats2half2_rn(a, b);
}

template <typename OutT>
__device__ __forceinline__ void gemm_body(
    uint32_t sb, const __half* __restrict__ A, const __half* __restrict__ Wt,
    const float* __restrict__ bias, OutT* __restrict__ C,
    int bm, int bn)
{
    const int tid  = threadIdx.x;
    const int wid  = tid >> 5;
    const int lane = tid & 31;
    const int wm   = wid & 1;
    const int wn   = wid >> 1;

    const int lr = tid >> 3;            // 0..31
    const int lq = tid & 7;             // 16B chunk

    float acc[4][4][4];
    #pragma unroll
    for (int a = 0; a < 4; ++a)
        #pragma unroll
        for (int b = 0; b < 4; ++b)
            #pragma unroll
            for (int c = 0; c < 4; ++c) acc[a][b][c] = 0.f;

    auto load_stage = [&](int s, int kt) {
        const int kb = kt * 64;
        const uint32_t base = (uint32_t)(s * STG_SZ);
        #pragma unroll
        for (int i = 0; i < 4; ++i) {
            const int row = i * 32 + lr;
            const uint32_t so = base + (uint32_t)(row * ROWB + lq * 16);
            cp16(sb + so, A + (size_t)(bm + row) * CC + kb + lq * 8);
            cp16(sb + OFF_B + so, Wt + (size_t)(bn + row) * CC + kb + lq * 8);
        }
    };

    load_stage(0, 0);
    CP_COMMIT();

    const int sub16 = lane & 15;
    const int ahalf = lane >> 4;
    const int bn8   = lane & 7;
    const int bk16  = (lane >> 3) & 1;

    #pragma unroll 1
    for (int kt = 0; kt < 8; ++kt) {
        const int s = kt & 1;
        CP_WAIT(0);
        __syncthreads();
        if (kt + 1 < 8) {
            load_stage(s ^ 1, kt + 1);
            CP_COMMIT();
        }

        const uint32_t aBase = sb + (uint32_t)(s * STG_SZ);
        const uint32_t bBase = aBase + OFF_B;

        #pragma unroll
        for (int s2 = 0; s2 < 4; ++s2) {
            const int kbyte = s2 * 32;

            uint32_t bh[4][2];
            #pragma unroll
            for (int nf = 0; nf < 4; ++nf) {
                const uint32_t brow = (uint32_t)(wn * 32 + nf * 8 + bn8);
                const uint32_t ba = bBase + brow * ROWB + kbyte + bk16 * 16;
                asm volatile(
                    "ldmatrix.sync.aligned.m8n8.x2.shared.b16 {%0,%1}, [%2];"
                    : "=r"(bh[nf][0]), "=r"(bh[nf][1]) : "r"(ba));
            }
            uint32_t ah[4][4];
            #pragma unroll
            for (int mf = 0; mf < 4; ++mf) {
                const uint32_t arow = (uint32_t)(wm * 64 + mf * 16 + sub16);
                const uint32_t aa = aBase + arow * ROWB + kbyte + ahalf * 16;
                asm volatile(
                    "ldmatrix.sync.aligned.m8n8.x4.shared.b16 {%0,%1,%2,%3}, [%4];"
                    : "=r"(ah[mf][0]), "=r"(ah[mf][1]), "=r"(ah[mf][2]), "=r"(ah[mf][3])
                    : "r"(aa));
            }

            #pragma unroll
            for (int mf = 0; mf < 4; ++mf)
                #pragma unroll
                for (int nf = 0; nf < 4; ++nf)
                    MMA_F16(acc[mf][nf], ah[mf][0], ah[mf][1], ah[mf][2], ah[mf][3],
                            bh[nf][0], bh[nf][1]);
        }
    }

    const int g = lane >> 2;
    const int t = lane & 3;
    #pragma unroll
    for (int mf = 0; mf < 4; ++mf) {
        const int row = bm + wm * 64 + mf * 16 + g;
        #pragma unroll
        for (int nf = 0; nf < 4; ++nf) {
            const int col = wn * 32 + nf * 8 + 2 * t;       // local col in [0,128)
            const float b0 = __ldg(bias + col);
            const float b1 = __ldg(bias + col + 1);
            float* d = acc[mf][nf];
            store2<OutT>(C + (size_t)row * CC + col, d[0] + b0, d[1] + b1);
            store2<OutT>(C + (size_t)(row + 8) * CC + col, d[2] + b0, d[3] + b1);
        }
    }
}

// standard single-output GEMM
template <typename OutT>
__global__ void __launch_bounds__(256, 2) mma_gemm_bias(
    const __half* __restrict__ A, const __half* __restrict__ Wt,
    const float* __restrict__ bias, OutT* __restrict__ C)
{
    extern __shared__ char sm[];
    const uint32_t sb = smem_to_u32(sm);
    const int bm = blockIdx.y * 128;
    const int bn = blockIdx.x * 128;
    gemm_body<OutT>(sb, A, Wt, bias + bn, C + bn, bm, bn);
}

// fused K+V GEMM: blockIdx.x in [0,8); <4 -> K weight/out, else V
__global__ void __launch_bounds__(256, 2) mma_gemm_bias_kv(
    const __half* __restrict__ A,
    const __half* __restrict__ Wk, const __half* __restrict__ Wv,
    const float* __restrict__ bk, const float* __restrict__ bv,
    __half* __restrict__ Ck, __half* __restrict__ Cv)
{
    extern __shared__ char sm[];
    const uint32_t sb = smem_to_u32(sm);
    const int bm = blockIdx.y * 128;
    const bool is_v = blockIdx.x >= 4;
    const int bn = (blockIdx.x & 3) * 128;
    const __half* W = is_v ? Wv : Wk;
    const float*  b = is_v ? bv : bk;
    __half*       C = is_v ? Cv : Ck;
    gemm_body<__half>(sb, A, W, b + bn, C + bn, bm, bn);
}

// ---------------- gather attention: fp16 K/V, one warp per (b,q) ------------
__global__ void __launch_bounds__(256) attn_kernel(
    const float* __restrict__ q, const __half* __restrict__ k,
    const __half* __restrict__ v, const int* __restrict__ indices,
    const float* __restrict__ weights, __half* __restrict__ oh)
{
    __shared__ float slog[8 * 8 * 33];
    const int wid  = threadIdx.x >> 5;
    const int lane = threadIdx.x & 31;
    const int bq   = blockIdx.x * 8 + wid;
    const int b    = bq >> 12;
    float* sl = slog + wid * (8 * 33);

    const __half* kb = k + (size_t)b * NTGT * CC;
    const __half* vb = v + (size_t)b * NTGT * CC;

    const int idxl = indices[(size_t)bq * KNN + lane];

    float qf[2][8];
    {
        const float4* qrow = reinterpret_cast<const float4*>(q + (size_t)bq * CC);
        #pragma unroll
        for (int i = 0; i < 2; ++i) {
            float4 a = qrow[i * 64 + lane * 2];
            float4 c = qrow[i * 64 + lane * 2 + 1];
            qf[i][0] = a.x; qf[i][1] = a.y; qf[i][2] = a.z; qf[i][3] = a.w;
            qf[i][4] = c.x; qf[i][5] = c.y; qf[i][6] = c.z; qf[i][7] = c.w;
        }
    }

    #pragma unroll 4
    for (int j = 0; j < KNN; ++j) {
        const int ij = __shfl_sync(0xffffffffu, idxl, j);
        const uint4* krow = reinterpret_cast<const uint4*>(kb + (size_t)ij * CC);
        float part[2];
        #pragma unroll
        for (int i = 0; i < 2; ++i) {
            const uint4 kk = krow[i * 32 + lane];
            const __half2* kh = reinterpret_cast<const __half2*>(&kk);
            float p = 0.f;
            #pragma unroll
            for (int h2 = 0; h2 < 4; ++h2) {
                const float2 kf = __half22float2(kh[h2]);
                p = fmaf(qf[i][2 * h2], kf.x, p);
                p = fmaf(qf[i][2 * h2 + 1], kf.y, p);
            }
            part[i] = p;
        }
        #pragma unroll
        for (int off = 4; off >= 1; off >>= 1) {
            part[0] += __shfl_xor_sync(0xffffffffu, part[0], off);
            part[1] += __shfl_xor_sync(0xffffffffu, part[1], off);
        }
        if ((lane & 7) == 0) {
            sl[(0 * 4 + (lane >> 3)) * 33 + j] = part[0];
            sl[(1 * 4 + (lane >> 3)) * 33 + j] = part[1];
        }
    }
    __syncwarp();

    {
        const int h  = lane >> 2;
        const int j0 = lane & 3;
        float vals[8];
        #pragma unroll
        for (int t = 0; t < 8; ++t) {
            const int j = j0 + 4 * t;
            vals[t] = sl[h * 33 + j] * SCALE + weights[(size_t)bq * KNN + j];
        }
        float m = vals[0];
        #pragma unroll
        for (int t = 1; t < 8; ++t) m = fmaxf(m, vals[t]);
        m = fmaxf(m, __shfl_xor_sync(0xffffffffu, m, 1));
        m = fmaxf(m, __shfl_xor_sync(0xffffffffu, m, 2));
        float s = 0.f;
        #pragma unroll
        for (int t = 0; t < 8; ++t) { vals[t] = __expf(vals[t] - m); s += vals[t]; }
        s += __shfl_xor_sync(0xffffffffu, s, 1);
        s += __shfl_xor_sync(0xffffffffu, s, 2);
        const float inv = 1.f / s;
        #pragma unroll
        for (int t = 0; t < 8; ++t) sl[h * 33 + j0 + 4 * t] = vals[t] * inv;
    }
    __syncwarp();

    float acc[2][8];
    #pragma unroll
    for (int i = 0; i < 2; ++i)
        #pragma unroll
        for (int d = 0; d < 8; ++d) acc[i][d] = 0.f;

    const int hsub = lane >> 3;
    #pragma unroll 4
    for (int j = 0; j < KNN; ++j) {
        const int ij = __shfl_sync(0xffffffffu, idxl, j);
        const uint4* vrow = reinterpret_cast<const uint4*>(vb + (size_t)ij * CC);
        #pragma unroll
        for (int i = 0; i < 2; ++i) {
            const float pj = sl[(i * 4 + hsub) * 33 + j];
            const uint4 vv = vrow[i * 32 + lane];
            const __half2* vh = reinterpret_cast<const __half2*>(&vv);
            #pragma unroll
            for (int h2 = 0; h2 < 4; ++h2) {
                const float2 vf = __half22float2(vh[h2]);
                acc[i][2 * h2]     = fmaf(pj, vf.x, acc[i][2 * h2]);
                acc[i][2 * h2 + 1] = fmaf(pj, vf.y, acc[i][2 * h2 + 1]);
            }
        }
    }

    #pragma unroll
    for (int i = 0; i < 2; ++i) {
        const size_t d = (size_t)bq * CC + i * 256 + lane * 8;
        uint32_t hw[4];
        #pragma unroll
        for (int p = 0; p < 4; ++p)
            hw[p] = pack2h(__float2half_rn(acc[i][2 * p]),
                           __float2half_rn(acc[i][2 * p + 1]));
        *reinterpret_cast<uint4*>(oh + d) = make_uint4(hw[0], hw[1], hw[2], hw[3]);
    }
}

// ---------------- launch ----------------------------------------------------
extern "C" void kernel_launch(void* const* d_in, const int* in_sizes, int n_in,
                              void* d_out, int out_size)
{
    const float* src = (const float*)d_in[0];
    const float* tgt = (const float*)d_in[1];
    const int*   idx = (const int*)d_in[2];
    const float* wts = (const float*)d_in[3];
    const float* Wq  = (const float*)d_in[4];
    const float* bq  = (const float*)d_in[5];
    const float* Wk  = (const float*)d_in[6];
    const float* bk  = (const float*)d_in[7];
    const float* Wv  = (const float*)d_in[8];
    const float* bv  = (const float*)d_in[9];
    const float* Wo  = (const float*)d_in[10];
    const float* bo  = (const float*)d_in[11];
    float*       out = (float*)d_out;

    void *pq, *pkh, *pvh, *psh, *pth, *poh, *pwt;
    cudaGetSymbolAddress(&pq, g_q);
    cudaGetSymbolAddress(&pkh, g_kh);
    cudaGetSymbolAddress(&pvh, g_vh);
    cudaGetSymbolAddress(&psh, g_Sh);
    cudaGetSymbolAddress(&pth, g_Th);
    cudaGetSymbolAddress(&poh, g_Oh);
    cudaGetSymbolAddress(&pwt, g_Wt);
    float*  gq  = (float*)pq;
    __half* gkh = (__half*)pkh;
    __half* gvh = (__half*)pvh;
    __half* sh  = (__half*)psh;
    __half* th  = (__half*)pth;
    __half* oh  = (__half*)poh;
    __half* wt  = (__half*)pwt;

    static bool attr_set = false;
    if (!attr_set) {
        cudaFuncSetAttribute(mma_gemm_bias<float>,
                             cudaFuncAttributeMaxDynamicSharedMemorySize, SM_TOT);
        cudaFuncSetAttribute(mma_gemm_bias<__half>,
                             cudaFuncAttributeMaxDynamicSharedMemorySize, SM_TOT);
        cudaFuncSetAttribute(mma_gemm_bias_kv,
                             cudaFuncAttributeMaxDynamicSharedMemorySize, SM_TOT);
        attr_set = true;
    }

    const size_t WS = (size_t)CC * CC;

    dim3 tgrid(CC / 32, CC / 32, 4), tblk(32, 8);
    transpose_half_all<<<tgrid, tblk>>>(Wq, Wk, Wv, Wo, wt);

    const int nconv = MROWS * CC / 4 / 256;
    conv2_kernel<<<2 * nconv, 256>>>(src, tgt, sh, th);

    dim3 ggrid(CC / 128, MROWS / 128);       // (4, 64)
    dim3 kvgrid(2 * CC / 128, MROWS / 128);  // (8, 64)

    mma_gemm_bias<float><<<ggrid, 256, SM_TOT>>>(sh, wt + 0 * WS, bq, gq);
    mma_gemm_bias_kv<<<kvgrid, 256, SM_TOT>>>(th, wt + 1 * WS, wt + 2 * WS,
                                              bk, bv, gkh, gvh);

    attn_kernel<<<BB * HW / 8, 256>>>(gq, gkh, gvh, idx, wts, oh);

    mma_gemm_bias<float><<<ggrid, 256, SM_TOT>>>(oh, wt + 3 * WS, bo, out);
}

// round 14
// speedup vs baseline: 1.4147x; 1.0197x over previous
#include <cuda_runtime.h>
#include <cuda_bf16.h>
#include <cuda_fp16.h>
#include <cstdint>

// Problem constants
#define BB    2
#define HW    4096
#define NTGT  4096
#define CC    512
#define HH    8
#define KNN   32
#define DH    64
#define MROWS (BB * HW)      // 8192
#define SCALE 0.125f

// ---------------- scratch (device globals: allocation-free) ----------------
__device__ __half g_qh[(size_t)MROWS * CC];
__device__ __half g_kh[(size_t)MROWS * CC];
__device__ __half g_vh[(size_t)MROWS * CC];
__device__ __half g_Sh[(size_t)MROWS * CC];    // src fp16
__device__ __half g_Th[(size_t)MROWS * CC];    // tgt fp16
__device__ __half g_Oh[(size_t)MROWS * CC];    // attn-out fp16
__device__ __half g_Wt[4][CC * CC];            // [N][K] fp16

// ---------------- helpers ----------------------------------------------------
__device__ __forceinline__ uint32_t smem_to_u32(const void* p) {
    uint32_t a;
    asm("{ .reg .u64 t; cvta.to.shared.u64 t, %1; cvt.u32.u64 %0, t; }"
        : "=r"(a) : "l"(p));
    return a;
}
__device__ __forceinline__ void cp16(uint32_t dst, const void* src) {
    asm volatile("cp.async.cg.shared.global [%0], [%1], 16;" :: "r"(dst), "l"(src));
}
#define CP_COMMIT() asm volatile("cp.async.commit_group;" ::: "memory")
#define CP_WAIT(n)  asm volatile("cp.async.wait_group %0;" :: "n"(n) : "memory")

__device__ __forceinline__ uint32_t pack2h(__half a, __half b) {
    __half2 t = __halves2half2(a, b);
    return *reinterpret_cast<uint32_t*>(&t);
}

#define MMA_F16(d, a0, a1, a2, a3, b0, b1) \
    asm volatile( \
        "mma.sync.aligned.m16n8k16.row.col.f32.f16.f16.f32 " \
        "{%0,%1,%2,%3}, {%4,%5,%6,%7}, {%8,%9}, {%0,%1,%2,%3};" \
        : "+f"((d)[0]), "+f"((d)[1]), "+f"((d)[2]), "+f"((d)[3]) \
        : "r"(a0), "r"(a1), "r"(a2), "r"(a3), "r"(b0), "r"(b1))

// ---------------- fused weight transpose -> fp16 [N][K] ---------------------
__global__ void transpose_half_all(const float* __restrict__ W0,
                                   const float* __restrict__ W1,
                                   const float* __restrict__ W2,
                                   const float* __restrict__ W3,
                                   __half* __restrict__ out)
{
    __shared__ float t[32][33];
    const int w  = blockIdx.z;
    const float* W = (w == 0) ? W0 : (w == 1) ? W1 : (w == 2) ? W2 : W3;
    const size_t wo = (size_t)w * CC * CC;
    const int kt = blockIdx.x * 32;
    const int nt = blockIdx.y * 32;
    const int tx = threadIdx.x, ty = threadIdx.y;
    #pragma unroll
    for (int i = 0; i < 4; ++i)
        t[ty + i * 8][tx] = W[(size_t)(kt + ty + i * 8) * CC + nt + tx];
    __syncthreads();
    #pragma unroll
    for (int i = 0; i < 4; ++i) {
        float x = t[tx][ty + i * 8];
        out[wo + (size_t)(nt + ty + i * 8) * CC + kt + tx] = __float2half_rn(x);
    }
}

// ---------------- fused activation convert: src + tgt -> fp16 --------------
__global__ void __launch_bounds__(256) conv2_kernel(
    const float* __restrict__ S, const float* __restrict__ T,
    __half* __restrict__ sh, __half* __restrict__ th)
{
    const int half = gridDim.x >> 1;
    const bool is_t = blockIdx.x >= half;
    const float* X = is_t ? T : S;
    __half* o = is_t ? th : sh;
    const int i = (is_t ? blockIdx.x - half : blockIdx.x) * 256 + threadIdx.x;
    const float4 x = reinterpret_cast<const float4*>(X)[i];
    reinterpret_cast<uint2*>(o)[i] =
        make_uint2(pack2h(__float2half_rn(x.x), __float2half_rn(x.y)),
                   pack2h(__float2half_rn(x.z), __float2half_rn(x.w)));
}

// ---------------- fp16 single-term mma GEMM body ----------------------------
#define ROWB 144                        // 128B data + 16B pad
#define REG_SZ (128 * ROWB)             // 18432 per region (128 rows)
#define STG_SZ (2 * REG_SZ)             // [A | B]
#define OFF_B  REG_SZ
#define SM_TOT (2 * STG_SZ)             // 73728

template <typename OutT>
__device__ __forceinline__ void store2(OutT* p, float a, float b);
template <> __device__ __forceinline__ void store2<float>(float* p, float a, float b) {
    *reinterpret_cast<float2*>(p) = make_float2(a, b);
}
template <> __device__ __forceinline__ void store2<__half>(__half* p, float a, float b) {
    *reinterpret_cast<__half2*>(p) = __floats2half2_rn(a, b);
}

template <typename OutT>
__device__ __forceinline__ void gemm_body(
    uint32_t sb, const __half* __restrict__ A, const __half* __restrict__ Wt,
    const float* __restrict__ bias, OutT* __restrict__ C,
    int bm, int bn)
{
    const int tid  = threadIdx.x;
    const int wid  = tid >> 5;
    const int lane = tid & 31;
    const int wm   = wid & 1;
    const int wn   = wid >> 1;

    const int lr = tid >> 3;            // 0..31
    const int lq = tid & 7;             // 16B chunk

    float acc[4][4][4];
    #pragma unroll
    for (int a = 0; a < 4; ++a)
        #pragma unroll
        for (int b = 0; b < 4; ++b)
            #pragma unroll
            for (int c = 0; c < 4; ++c) acc[a][b][c] = 0.f;

    auto load_stage = [&](int s, int kt) {
        const int kb = kt * 64;
        const uint32_t base = (uint32_t)(s * STG_SZ);
        #pragma unroll
        for (int i = 0; i < 4; ++i) {
            const int row = i * 32 + lr;
            const uint32_t so = base + (uint32_t)(row * ROWB + lq * 16);
            cp16(sb + so, A + (size_t)(bm + row) * CC + kb + lq * 8);
            cp16(sb + OFF_B + so, Wt + (size_t)(bn + row) * CC + kb + lq * 8);
        }
    };

    load_stage(0, 0);
    CP_COMMIT();

    const int sub16 = lane & 15;
    const int ahalf = lane >> 4;
    const int bn8   = lane & 7;
    const int bk16  = (lane >> 3) & 1;

    #pragma unroll 1
    for (int kt = 0; kt < 8; ++kt) {
        const int s = kt & 1;
        CP_WAIT(0);
        __syncthreads();
        if (kt + 1 < 8) {
            load_stage(s ^ 1, kt + 1);
            CP_COMMIT();
        }

        const uint32_t aBase = sb + (uint32_t)(s * STG_SZ);
        const uint32_t bBase = aBase + OFF_B;

        #pragma unroll
        for (int s2 = 0; s2 < 4; ++s2) {
            const int kbyte = s2 * 32;

            uint32_t bh[4][2];
            #pragma unroll
            for (int nf = 0; nf < 4; ++nf) {
                const uint32_t brow = (uint32_t)(wn * 32 + nf * 8 + bn8);
                const uint32_t ba = bBase + brow * ROWB + kbyte + bk16 * 16;
                asm volatile(
                    "ldmatrix.sync.aligned.m8n8.x2.shared.b16 {%0,%1}, [%2];"
                    : "=r"(bh[nf][0]), "=r"(bh[nf][1]) : "r"(ba));
            }
            uint32_t ah[4][4];
            #pragma unroll
            for (int mf = 0; mf < 4; ++mf) {
                const uint32_t arow = (uint32_t)(wm * 64 + mf * 16 + sub16);
                const uint32_t aa = aBase + arow * ROWB + kbyte + ahalf * 16;
                asm volatile(
                    "ldmatrix.sync.aligned.m8n8.x4.shared.b16 {%0,%1,%2,%3}, [%4];"
                    : "=r"(ah[mf][0]), "=r"(ah[mf][1]), "=r"(ah[mf][2]), "=r"(ah[mf][3])
                    : "r"(aa));
            }

            #pragma unroll
            for (int mf = 0; mf < 4; ++mf)
                #pragma unroll
                for (int nf = 0; nf < 4; ++nf)
                    MMA_F16(acc[mf][nf], ah[mf][0], ah[mf][1], ah[mf][2], ah[mf][3],
                            bh[nf][0], bh[nf][1]);
        }
    }

    const int g = lane >> 2;
    const int t = lane & 3;
    #pragma unroll
    for (int mf = 0; mf < 4; ++mf) {
        const int row = bm + wm * 64 + mf * 16 + g;
        #pragma unroll
        for (int nf = 0; nf < 4; ++nf) {
            const int col = wn * 32 + nf * 8 + 2 * t;       // local col in [0,128)
            const float b0 = __ldg(bias + col);
            const float b1 = __ldg(bias + col + 1);
            float* d = acc[mf][nf];
            store2<OutT>(C + (size_t)row * CC + col, d[0] + b0, d[1] + b1);
            store2<OutT>(C + (size_t)(row + 8) * CC + col, d[2] + b0, d[3] + b1);
        }
    }
}

// standard single-output GEMM (used for the O projection, float out)
template <typename OutT>
__global__ void __launch_bounds__(256, 2) mma_gemm_bias(
    const __half* __restrict__ A, const __half* __restrict__ Wt,
    const float* __restrict__ bias, OutT* __restrict__ C)
{
    extern __shared__ char sm[];
    const uint32_t sb = smem_to_u32(sm);
    const int bm = blockIdx.y * 128;
    const int bn = blockIdx.x * 128;
    gemm_body<OutT>(sb, A, Wt, bias + bn, C + bn, bm, bn);
}

// fused Q+K+V GEMM: blockIdx.x in [0,12); w = x>>2 selects projection
__global__ void __launch_bounds__(256, 2) mma_gemm_bias_qkv(
    const __half* __restrict__ Sh, const __half* __restrict__ Th,
    const __half* __restrict__ Wt,   // 3 weights, stride CC*CC
    const float* __restrict__ bq, const float* __restrict__ bk,
    const float* __restrict__ bv,
    __half* __restrict__ Cq, __half* __restrict__ Ck, __half* __restrict__ Cv)
{
    extern __shared__ char sm[];
    const uint32_t sb = smem_to_u32(sm);
    const int bm = blockIdx.y * 128;
    const int w  = blockIdx.x >> 2;       // 0=Q, 1=K, 2=V
    const int bn = (blockIdx.x & 3) * 128;
    const __half* A = (w == 0) ? Sh : Th;
    const __half* W = Wt + (size_t)w * CC * CC;
    const float*  b = (w == 0) ? bq : (w == 1) ? bk : bv;
    __half*       C = (w == 0) ? Cq : (w == 1) ? Ck : Cv;
    gemm_body<__half>(sb, A, W, b + bn, C + bn, bm, bn);
}

// ---------------- gather attention: fp16 Q/K/V, one warp per (b,q) ----------
__global__ void __launch_bounds__(256) attn_kernel(
    const __half* __restrict__ q, const __half* __restrict__ k,
    const __half* __restrict__ v, const int* __restrict__ indices,
    const float* __restrict__ weights, __half* __restrict__ oh)
{
    __shared__ float slog[8 * 8 * 33];
    const int wid  = threadIdx.x >> 5;
    const int lane = threadIdx.x & 31;
    const int bq   = blockIdx.x * 8 + wid;
    const int b    = bq >> 12;
    float* sl = slog + wid * (8 * 33);

    const __half* kb = k + (size_t)b * NTGT * CC;
    const __half* vb = v + (size_t)b * NTGT * CC;

    const int idxl = indices[(size_t)bq * KNN + lane];

    float qf[2][8];
    {
        const uint4* qrow = reinterpret_cast<const uint4*>(q + (size_t)bq * CC);
        #pragma unroll
        for (int i = 0; i < 2; ++i) {
            const uint4 qq = qrow[i * 32 + lane];
            const __half2* qh2 = reinterpret_cast<const __half2*>(&qq);
            #pragma unroll
            for (int h2 = 0; h2 < 4; ++h2) {
                const float2 f = __half22float2(qh2[h2]);
                qf[i][2 * h2]     = f.x;
                qf[i][2 * h2 + 1] = f.y;
            }
        }
    }

    #pragma unroll 4
    for (int j = 0; j < KNN; ++j) {
        const int ij = __shfl_sync(0xffffffffu, idxl, j);
        const uint4* krow = reinterpret_cast<const uint4*>(kb + (size_t)ij * CC);
        float part[2];
        #pragma unroll
        for (int i = 0; i < 2; ++i) {
            const uint4 kk = krow[i * 32 + lane];
            const __half2* kh = reinterpret_cast<const __half2*>(&kk);
            float p = 0.f;
            #pragma unroll
            for (int h2 = 0; h2 < 4; ++h2) {
                const float2 kf = __half22float2(kh[h2]);
                p = fmaf(qf[i][2 * h2], kf.x, p);
                p = fmaf(qf[i][2 * h2 + 1], kf.y, p);
            }
            part[i] = p;
        }
        #pragma unroll
        for (int off = 4; off >= 1; off >>= 1) {
            part[0] += __shfl_xor_sync(0xffffffffu, part[0], off);
            part[1] += __shfl_xor_sync(0xffffffffu, part[1], off);
        }
        if ((lane & 7) == 0) {
            sl[(0 * 4 + (lane >> 3)) * 33 + j] = part[0];
            sl[(1 * 4 + (lane >> 3)) * 33 + j] = part[1];
        }
    }
    __syncwarp();

    {
        const int h  = lane >> 2;
        const int j0 = lane & 3;
        float vals[8];
        #pragma unroll
        for (int t = 0; t < 8; ++t) {
            const int j = j0 + 4 * t;
            vals[t] = sl[h * 33 + j] * SCALE + weights[(size_t)bq * KNN + j];
        }
        float m = vals[0];
        #pragma unroll
        for (int t = 1; t < 8; ++t) m = fmaxf(m, vals[t]);
        m = fmaxf(m, __shfl_xor_sync(0xffffffffu, m, 1));
        m = fmaxf(m, __shfl_xor_sync(0xffffffffu, m, 2));
        float s = 0.f;
        #pragma unroll
        for (int t = 0; t < 8; ++t) { vals[t] = __expf(vals[t] - m); s += vals[t]; }
        s += __shfl_xor_sync(0xffffffffu, s, 1);
        s += __shfl_xor_sync(0xffffffffu, s, 2);
        const float inv = 1.f / s;
        #pragma unroll
        for (int t = 0; t < 8; ++t) sl[h * 33 + j0 + 4 * t] = vals[t] * inv;
    }
    __syncwarp();

    float acc[2][8];
    #pragma unroll
    for (int i = 0; i < 2; ++i)
        #pragma unroll
        for (int d = 0; d < 8; ++d) acc[i][d] = 0.f;

    const int hsub = lane >> 3;
    #pragma unroll 4
    for (int j = 0; j < KNN; ++j) {
        const int ij = __shfl_sync(0xffffffffu, idxl, j);
        const uint4* vrow = reinterpret_cast<const uint4*>(vb + (size_t)ij * CC);
        #pragma unroll
        for (int i = 0; i < 2; ++i) {
            const float pj = sl[(i * 4 + hsub) * 33 + j];
            const uint4 vv = vrow[i * 32 + lane];
            const __half2* vh = reinterpret_cast<const __half2*>(&vv);
            #pragma unroll
            for (int h2 = 0; h2 < 4; ++h2) {
                const float2 vf = __half22float2(vh[h2]);
                acc[i][2 * h2]     = fmaf(pj, vf.x, acc[i][2 * h2]);
                acc[i][2 * h2 + 1] = fmaf(pj, vf.y, acc[i][2 * h2 + 1]);
            }
        }
    }

    #pragma unroll
    for (int i = 0; i < 2; ++i) {
        const size_t d = (size_t)bq * CC + i * 256 + lane * 8;
        uint32_t hw[4];
        #pragma unroll
        for (int p = 0; p < 4; ++p)
            hw[p] = pack2h(__float2half_rn(acc[i][2 * p]),
                           __float2half_rn(acc[i][2 * p + 1]));
        *reinterpret_cast<uint4*>(oh + d) = make_uint4(hw[0], hw[1], hw[2], hw[3]);
    }
}

// ---------------- launch ----------------------------------------------------
extern "C" void kernel_launch(void* const* d_in, const int* in_sizes, int n_in,
                              void* d_out, int out_size)
{
    const float* src = (const float*)d_in[0];
    const float* tgt = (const float*)d_in[1];
    const int*   idx = (const int*)d_in[2];
    const float* wts = (const float*)d_in[3];
    const float* Wq  = (const float*)d_in[4];
    const float* bq  = (const float*)d_in[5];
    const float* Wk  = (const float*)d_in[6];
    const float* bk  = (const float*)d_in[7];
    const float* Wv  = (const float*)d_in[8];
    const float* bv  = (const float*)d_in[9];
    const float* Wo  = (const float*)d_in[10];
    const float* bo  = (const float*)d_in[11];
    float*       out = (float*)d_out;

    void *pqh, *pkh, *pvh, *psh, *pth, *poh, *pwt;
    cudaGetSymbolAddress(&pqh, g_qh);
    cudaGetSymbolAddress(&pkh, g_kh);
    cudaGetSymbolAddress(&pvh, g_vh);
    cudaGetSymbolAddress(&psh, g_Sh);
    cudaGetSymbolAddress(&pth, g_Th);
    cudaGetSymbolAddress(&poh, g_Oh);
    cudaGetSymbolAddress(&pwt, g_Wt);
    __half* gqh = (__half*)pqh;
    __half* gkh = (__half*)pkh;
    __half* gvh = (__half*)pvh;
    __half* sh  = (__half*)psh;
    __half* th  = (__half*)pth;
    __half* oh  = (__half*)poh;
    __half* wt  = (__half*)pwt;

    static bool attr_set = false;
    if (!attr_set) {
        cudaFuncSetAttribute(mma_gemm_bias<float>,
                             cudaFuncAttributeMaxDynamicSharedMemorySize, SM_TOT);
        cudaFuncSetAttribute(mma_gemm_bias_qkv,
                             cudaFuncAttributeMaxDynamicSharedMemorySize, SM_TOT);
        attr_set = true;
    }

    const size_t WS = (size_t)CC * CC;

    dim3 tgrid(CC / 32, CC / 32, 4), tblk(32, 8);
    transpose_half_all<<<tgrid, tblk>>>(Wq, Wk, Wv, Wo, wt);

    const int nconv = MROWS * CC / 4 / 256;
    conv2_kernel<<<2 * nconv, 256>>>(src, tgt, sh, th);

    dim3 qkvgrid(3 * CC / 128, MROWS / 128);   // (12, 64) = 768 CTAs
    mma_gemm_bias_qkv<<<qkvgrid, 256, SM_TOT>>>(sh, th, wt,
                                                bq, bk, bv, gqh, gkh, gvh);

    attn_kernel<<<BB * HW / 8, 256>>>(gqh, gkh, gvh, idx, wts, oh);

    dim3 ggrid(CC / 128, MROWS / 128);         // (4, 64)
    mma_gemm_bias<float><<<ggrid, 256, SM_TOT>>>(oh, wt + 3 * WS, bo, out);
}

// round 15
// speedup vs baseline: 1.4435x; 1.0203x over previous
#include <cuda_runtime.h>
#include <cuda_bf16.h>
#include <cuda_fp16.h>
#include <cstdint>

// Problem constants
#define BB    2
#define HW    4096
#define NTGT  4096
#define CC    512
#define HH    8
#define KNN   32
#define DH    64
#define MROWS (BB * HW)      // 8192
#define SCALE 0.125f

// ---------------- scratch (device globals: allocation-free) ----------------
__device__ __half g_qh[(size_t)MROWS * CC];
__device__ __half g_kh[(size_t)MROWS * CC];
__device__ __half g_vh[(size_t)MROWS * CC];
__device__ __half g_Sh[(size_t)MROWS * CC];    // src fp16
__device__ __half g_Th[(size_t)MROWS * CC];    // tgt fp16
__device__ __half g_Oh[(size_t)MROWS * CC];    // attn-out fp16
__device__ __half g_Wt[4][CC * CC];            // [N][K] fp16

// ---------------- helpers ----------------------------------------------------
__device__ __forceinline__ uint32_t smem_to_u32(const void* p) {
    uint32_t a;
    asm("{ .reg .u64 t; cvta.to.shared.u64 t, %1; cvt.u32.u64 %0, t; }"
        : "=r"(a) : "l"(p));
    return a;
}
__device__ __forceinline__ void cp16(uint32_t dst, const void* src) {
    asm volatile("cp.async.cg.shared.global [%0], [%1], 16;" :: "r"(dst), "l"(src));
}
#define CP_COMMIT() asm volatile("cp.async.commit_group;" ::: "memory")
#define CP_WAIT(n)  asm volatile("cp.async.wait_group %0;" :: "n"(n) : "memory")

__device__ __forceinline__ uint32_t pack2h(__half a, __half b) {
    __half2 t = __halves2half2(a, b);
    return *reinterpret_cast<uint32_t*>(&t);
}

#define MMA_F16(d, a0, a1, a2, a3, b0, b1) \
    asm volatile( \
        "mma.sync.aligned.m16n8k16.row.col.f32.f16.f16.f32 " \
        "{%0,%1,%2,%3}, {%4,%5,%6,%7}, {%8,%9}, {%0,%1,%2,%3};" \
        : "+f"((d)[0]), "+f"((d)[1]), "+f"((d)[2]), "+f"((d)[3]) \
        : "r"(a0), "r"(a1), "r"(a2), "r"(a3), "r"(b0), "r"(b1))

// ---------------- fused prep: weight transpose (4x) + src/tgt fp16 convert --
// blocks [0, 1024): transpose; blocks [1024, 9216): convert
__global__ void __launch_bounds__(256) prep_kernel(
    const float* __restrict__ W0, const float* __restrict__ W1,
    const float* __restrict__ W2, const float* __restrict__ W3,
    __half* __restrict__ wt,
    const float* __restrict__ S, const float* __restrict__ T,
    __half* __restrict__ sh, __half* __restrict__ th)
{
    const int bid = blockIdx.x;
    const int tid = threadIdx.x;
    if (bid < 1024) {
        __shared__ float t[32][33];
        const int w   = bid >> 8;
        const int rem = bid & 255;
        const int kt  = (rem & 15) * 32;
        const int nt  = (rem >> 4) * 32;
        const float* W = (w == 0) ? W0 : (w == 1) ? W1 : (w == 2) ? W2 : W3;
        const size_t wo = (size_t)w * CC * CC;
        const int tx = tid & 31, ty = tid >> 5;   // (32, 8)
        #pragma unroll
        for (int i = 0; i < 4; ++i)
            t[ty + i * 8][tx] = W[(size_t)(kt + ty + i * 8) * CC + nt + tx];
        __syncthreads();
        #pragma unroll
        for (int i = 0; i < 4; ++i) {
            float x = t[tx][ty + i * 8];
            wt[wo + (size_t)(nt + ty + i * 8) * CC + kt + tx] = __float2half_rn(x);
        }
    } else {
        const int cb = bid - 1024;                // 0..8191
        const bool is_t = cb >= 4096;
        const float* X = is_t ? T : S;
        __half* o = is_t ? th : sh;
        const int i = (is_t ? cb - 4096 : cb) * 256 + tid;
        const float4 x = reinterpret_cast<const float4*>(X)[i];
        reinterpret_cast<uint2*>(o)[i] =
            make_uint2(pack2h(__float2half_rn(x.x), __float2half_rn(x.y)),
                       pack2h(__float2half_rn(x.z), __float2half_rn(x.w)));
    }
}

// ---------------- fp16 single-term mma GEMM body (3-stage, BK=64) ----------
#define ROWB 144                        // 128B data + 16B pad
#define REG_SZ (128 * ROWB)             // 18432 per region (128 rows)
#define STG_SZ (2 * REG_SZ)             // [A | B] = 36864
#define OFF_B  REG_SZ
#define SM_TOT (3 * STG_SZ)             // 110592

template <typename OutT>
__device__ __forceinline__ void store2(OutT* p, float a, float b);
template <> __device__ __forceinline__ void store2<float>(float* p, float a, float b) {
    *reinterpret_cast<float2*>(p) = make_float2(a, b);
}
template <> __device__ __forceinline__ void store2<__half>(__half* p, float a, float b) {
    *reinterpret_cast<__half2*>(p) = __floats2half2_rn(a, b);
}

template <typename OutT>
__device__ __forceinline__ void gemm_body(
    uint32_t sb, const __half* __restrict__ A, const __half* __restrict__ Wt,
    const float* __restrict__ bias, OutT* __restrict__ C,
    int bm, int bn)
{
    const int tid  = threadIdx.x;
    const int wid  = tid >> 5;
    const int lane = tid & 31;
    const int wm   = wid & 1;
    const int wn   = wid >> 1;

    const int lr = tid >> 3;            // 0..31
    const int lq = tid & 7;             // 16B chunk

    float acc[4][4][4];
    #pragma unroll
    for (int a = 0; a < 4; ++a)
        #pragma unroll
        for (int b = 0; b < 4; ++b)
            #pragma unroll
            for (int c = 0; c < 4; ++c) acc[a][b][c] = 0.f;

    auto load_stage = [&](int s, int kt) {
        const int kb = kt * 64;
        const uint32_t base = (uint32_t)(s * STG_SZ);
        #pragma unroll
        for (int i = 0; i < 4; ++i) {
            const int row = i * 32 + lr;
            const uint32_t so = base + (uint32_t)(row * ROWB + lq * 16);
            cp16(sb + so, A + (size_t)(bm + row) * CC + kb + lq * 8);
            cp16(sb + OFF_B + so, Wt + (size_t)(bn + row) * CC + kb + lq * 8);
        }
    };

    load_stage(0, 0);
    CP_COMMIT();
    load_stage(1, 1);
    CP_COMMIT();

    const int sub16 = lane & 15;
    const int ahalf = lane >> 4;
    const int bn8   = lane & 7;
    const int bk16  = (lane >> 3) & 1;

    #pragma unroll 1
    for (int kt = 0; kt < 8; ++kt) {
        const int s = kt % 3;
        if (kt < 7) { CP_WAIT(1); } else { CP_WAIT(0); }
        __syncthreads();
        if (kt + 2 < 8) {
            load_stage((kt + 2) % 3, kt + 2);
            CP_COMMIT();
        }

        const uint32_t aBase = sb + (uint32_t)(s * STG_SZ);
        const uint32_t bBase = aBase + OFF_B;

        #pragma unroll
        for (int s2 = 0; s2 < 4; ++s2) {
            const int kbyte = s2 * 32;

            uint32_t bh[4][2];
            #pragma unroll
            for (int nf = 0; nf < 4; ++nf) {
                const uint32_t brow = (uint32_t)(wn * 32 + nf * 8 + bn8);
                const uint32_t ba = bBase + brow * ROWB + kbyte + bk16 * 16;
                asm volatile(
                    "ldmatrix.sync.aligned.m8n8.x2.shared.b16 {%0,%1}, [%2];"
                    : "=r"(bh[nf][0]), "=r"(bh[nf][1]) : "r"(ba));
            }
            uint32_t ah[4][4];
            #pragma unroll
            for (int mf = 0; mf < 4; ++mf) {
                const uint32_t arow = (uint32_t)(wm * 64 + mf * 16 + sub16);
                const uint32_t aa = aBase + arow * ROWB + kbyte + ahalf * 16;
                asm volatile(
                    "ldmatrix.sync.aligned.m8n8.x4.shared.b16 {%0,%1,%2,%3}, [%4];"
                    : "=r"(ah[mf][0]), "=r"(ah[mf][1]), "=r"(ah[mf][2]), "=r"(ah[mf][3])
                    : "r"(aa));
            }

            #pragma unroll
            for (int mf = 0; mf < 4; ++mf)
                #pragma unroll
                for (int nf = 0; nf < 4; ++nf)
                    MMA_F16(acc[mf][nf], ah[mf][0], ah[mf][1], ah[mf][2], ah[mf][3],
                            bh[nf][0], bh[nf][1]);
        }
    }

    const int g = lane >> 2;
    const int t = lane & 3;
    #pragma unroll
    for (int mf = 0; mf < 4; ++mf) {
        const int row = bm + wm * 64 + mf * 16 + g;
        #pragma unroll
        for (int nf = 0; nf < 4; ++nf) {
            const int col = wn * 32 + nf * 8 + 2 * t;       // local col in [0,128)
            const float b0 = __ldg(bias + col);
            const float b1 = __ldg(bias + col + 1);
            float* d = acc[mf][nf];
            store2<OutT>(C + (size_t)row * CC + col, d[0] + b0, d[1] + b1);
            store2<OutT>(C + (size_t)(row + 8) * CC + col, d[2] + b0, d[3] + b1);
        }
    }
}

// standard single-output GEMM (used for the O projection, float out)
template <typename OutT>
__global__ void __launch_bounds__(256, 2) mma_gemm_bias(
    const __half* __restrict__ A, const __half* __restrict__ Wt,
    const float* __restrict__ bias, OutT* __restrict__ C)
{
    extern __shared__ char sm[];
    const uint32_t sb = smem_to_u32(sm);
    const int bm = blockIdx.y * 128;
    const int bn = blockIdx.x * 128;
    gemm_body<OutT>(sb, A, Wt, bias + bn, C + bn, bm, bn);
}

// fused Q+K+V GEMM: blockIdx.x in [0,12); w = x>>2 selects projection
__global__ void __launch_bounds__(256, 2) mma_gemm_bias_qkv(
    const __half* __restrict__ Sh, const __half* __restrict__ Th,
    const __half* __restrict__ Wt,   // 3 weights, stride CC*CC
    const float* __restrict__ bq, const float* __restrict__ bk,
    const float* __restrict__ bv,
    __half* __restrict__ Cq, __half* __restrict__ Ck, __half* __restrict__ Cv)
{
    extern __shared__ char sm[];
    const uint32_t sb = smem_to_u32(sm);
    const int bm = blockIdx.y * 128;
    const int w  = blockIdx.x >> 2;       // 0=Q, 1=K, 2=V
    const int bn = (blockIdx.x & 3) * 128;
    const __half* A = (w == 0) ? Sh : Th;
    const __half* W = Wt + (size_t)w * CC * CC;
    const float*  b = (w == 0) ? bq : (w == 1) ? bk : bv;
    __half*       C = (w == 0) ? Cq : (w == 1) ? Ck : Cv;
    gemm_body<__half>(sb, A, W, b + bn, C + bn, bm, bn);
}

// ---------------- gather attention: fp16 Q/K/V, one warp per (b,q) ----------
__global__ void __launch_bounds__(256) attn_kernel(
    const __half* __restrict__ q, const __half* __restrict__ k,
    const __half* __restrict__ v, const int* __restrict__ indices,
    const float* __restrict__ weights, __half* __restrict__ oh)
{
    __shared__ float slog[8 * 8 * 33];
    const int wid  = threadIdx.x >> 5;
    const int lane = threadIdx.x & 31;
    const int bq   = blockIdx.x * 8 + wid;
    const int b    = bq >> 12;
    float* sl = slog + wid * (8 * 33);

    const __half* kb = k + (size_t)b * NTGT * CC;
    const __half* vb = v + (size_t)b * NTGT * CC;

    const int idxl = indices[(size_t)bq * KNN + lane];

    float qf[2][8];
    {
        const uint4* qrow = reinterpret_cast<const uint4*>(q + (size_t)bq * CC);
        #pragma unroll
        for (int i = 0; i < 2; ++i) {
            const uint4 qq = qrow[i * 32 + lane];
            const __half2* qh2 = reinterpret_cast<const __half2*>(&qq);
            #pragma unroll
            for (int h2 = 0; h2 < 4; ++h2) {
                const float2 f = __half22float2(qh2[h2]);
                qf[i][2 * h2]     = f.x;
                qf[i][2 * h2 + 1] = f.y;
            }
        }
    }

    #pragma unroll 4
    for (int j = 0; j < KNN; ++j) {
        const int ij = __shfl_sync(0xffffffffu, idxl, j);
        const uint4* krow = reinterpret_cast<const uint4*>(kb + (size_t)ij * CC);
        float part[2];
        #pragma unroll
        for (int i = 0; i < 2; ++i) {
            const uint4 kk = krow[i * 32 + lane];
            const __half2* kh = reinterpret_cast<const __half2*>(&kk);
            float p = 0.f;
            #pragma unroll
            for (int h2 = 0; h2 < 4; ++h2) {
                const float2 kf = __half22float2(kh[h2]);
                p = fmaf(qf[i][2 * h2], kf.x, p);
                p = fmaf(qf[i][2 * h2 + 1], kf.y, p);
            }
            part[i] = p;
        }
        #pragma unroll
        for (int off = 4; off >= 1; off >>= 1) {
            part[0] += __shfl_xor_sync(0xffffffffu, part[0], off);
            part[1] += __shfl_xor_sync(0xffffffffu, part[1], off);
        }
        if ((lane & 7) == 0) {
            sl[(0 * 4 + (lane >> 3)) * 33 + j] = part[0];
            sl[(1 * 4 + (lane >> 3)) * 33 + j] = part[1];
        }
    }
    __syncwarp();

    {
        const int h  = lane >> 2;
        const int j0 = lane & 3;
        float vals[8];
        #pragma unroll
        for (int t = 0; t < 8; ++t) {
            const int j = j0 + 4 * t;
            vals[t] = sl[h * 33 + j] * SCALE + weights[(size_t)bq * KNN + j];
        }
        float m = vals[0];
        #pragma unroll
        for (int t = 1; t < 8; ++t) m = fmaxf(m, vals[t]);
        m = fmaxf(m, __shfl_xor_sync(0xffffffffu, m, 1));
        m = fmaxf(m, __shfl_xor_sync(0xffffffffu, m, 2));
        float s = 0.f;
        #pragma unroll
        for (int t = 0; t < 8; ++t) { vals[t] = __expf(vals[t] - m); s += vals[t]; }
        s += __shfl_xor_sync(0xffffffffu, s, 1);
        s += __shfl_xor_sync(0xffffffffu, s, 2);
        const float inv = 1.f / s;
        #pragma unroll
        for (int t = 0; t < 8; ++t) sl[h * 33 + j0 + 4 * t] = vals[t] * inv;
    }
    __syncwarp();

    float acc[2][8];
    #pragma unroll
    for (int i = 0; i < 2; ++i)
        #pragma unroll
        for (int d = 0; d < 8; ++d) acc[i][d] = 0.f;

    const int hsub = lane >> 3;
    #pragma unroll 4
    for (int j = 0; j < KNN; ++j) {
        const int ij = __shfl_sync(0xffffffffu, idxl, j);
        const uint4* vrow = reinterpret_cast<const uint4*>(vb + (size_t)ij * CC);
        #pragma unroll
        for (int i = 0; i < 2; ++i) {
            const float pj = sl[(i * 4 + hsub) * 33 + j];
            const uint4 vv = vrow[i * 32 + lane];
            const __half2* vh = reinterpret_cast<const __half2*>(&vv);
            #pragma unroll
            for (int h2 = 0; h2 < 4; ++h2) {
                const float2 vf = __half22float2(vh[h2]);
                acc[i][2 * h2]     = fmaf(pj, vf.x, acc[i][2 * h2]);
                acc[i][2 * h2 + 1] = fmaf(pj, vf.y, acc[i][2 * h2 + 1]);
            }
        }
    }

    #pragma unroll
    for (int i = 0; i < 2; ++i) {
        const size_t d = (size_t)bq * CC + i * 256 + lane * 8;
        uint32_t hw[4];
        #pragma unroll
        for (int p = 0; p < 4; ++p)
            hw[p] = pack2h(__float2half_rn(acc[i][2 * p]),
                           __float2half_rn(acc[i][2 * p + 1]));
        *reinterpret_cast<uint4*>(oh + d) = make_uint4(hw[0], hw[1], hw[2], hw[3]);
    }
}

// ---------------- launch ----------------------------------------------------
extern "C" void kernel_launch(void* const* d_in, const int* in_sizes, int n_in,
                              void* d_out, int out_size)
{
    const float* src = (const float*)d_in[0];
    const float* tgt = (const float*)d_in[1];
    const int*   idx = (const int*)d_in[2];
    const float* wts = (const float*)d_in[3];
    const float* Wq  = (const float*)d_in[4];
    const float* bq  = (const float*)d_in[5];
    const float* Wk  = (const float*)d_in[6];
    const float* bk  = (const float*)d_in[7];
    const float* Wv  = (const float*)d_in[8];
    const float* bv  = (const float*)d_in[9];
    const float* Wo  = (const float*)d_in[10];
    const float* bo  = (const float*)d_in[11];
    float*       out = (float*)d_out;

    void *pqh, *pkh, *pvh, *psh, *pth, *poh, *pwt;
    cudaGetSymbolAddress(&pqh, g_qh);
    cudaGetSymbolAddress(&pkh, g_kh);
    cudaGetSymbolAddress(&pvh, g_vh);
    cudaGetSymbolAddress(&psh, g_Sh);
    cudaGetSymbolAddress(&pth, g_Th);
    cudaGetSymbolAddress(&poh, g_Oh);
    cudaGetSymbolAddress(&pwt, g_Wt);
    __half* gqh = (__half*)pqh;
    __half* gkh = (__half*)pkh;
    __half* gvh = (__half*)pvh;
    __half* sh  = (__half*)psh;
    __half* th  = (__half*)pth;
    __half* oh  = (__half*)poh;
    __half* wt  = (__half*)pwt;

    static bool attr_set = false;
    if (!attr_set) {
        cudaFuncSetAttribute(mma_gemm_bias<float>,
                             cudaFuncAttributeMaxDynamicSharedMemorySize, SM_TOT);
        cudaFuncSetAttribute(mma_gemm_bias_qkv,
                             cudaFuncAttributeMaxDynamicSharedMemorySize, SM_TOT);
        attr_set = true;
    }

    const size_t WS = (size_t)CC * CC;

    // fused prep: 1024 transpose blocks + 8192 convert blocks
    prep_kernel<<<9216, 256>>>(Wq, Wk, Wv, Wo, wt, src, tgt, sh, th);

    dim3 qkvgrid(3 * CC / 128, MROWS / 128);   // (12, 64) = 768 CTAs
    mma_gemm_bias_qkv<<<qkvgrid, 256, SM_TOT>>>(sh, th, wt,
                                                bq, bk, bv, gqh, gkh, gvh);

    attn_kernel<<<BB * HW / 8, 256>>>(gqh, gkh, gvh, idx, wts, oh);

    dim3 ggrid(CC / 128, MROWS / 128);         // (4, 64)
    mma_gemm_bias<float><<<ggrid, 256, SM_TOT>>>(oh, wt + 3 * WS, bo, out);
}